// round 14
// baseline (speedup 1.0000x reference)
#include <cuda_runtime.h>
#include <cstdint>
#include <cstddef>

// Problem dims
#define TT 1024
#define BB 64
#define HH 256
#define WPADI 260   // wih SMEM row stride (floats) — conflict-free w rows

// Dual-direction fused persistent kernel (R13 base + per-warp flags).
// 128 CTAs x 256 threads. Warps 0-3 = dir0 half, warps 4-7 = dir1 half.
// Each half: 16 hidden (48 gate rows) x 8 batches, K=256 both GEMMs.
// Thread (jg 0..15, ks 0..7) owns k-indices {c*32 + ks*4 + 0..3}.
//   x tiles: cp.async.bulk from g_x pre-pass, mbarrier, 1 step ahead.
//   h tiles: LDGSTS mid-GEMM after PARALLEL 64-flag poll.
//   Producer release: PER-WARP (bar.warp.sync + lane0 st.release) — no
//   producer-side half_bar on the h critical path.

__device__ float    g_x[TT][8][8][256];     // [t][grp][b][k] natural (64 MB)
__device__ float    g_h[2][2][8][8][256];   // [dir][buf][grp][b][k]
__device__ unsigned g_flag[2][8][16][4];    // per (dir,grp,slice,warp) flag
__device__ unsigned g_cnt[16 * 32];         // init barrier (128B-strided)
__device__ unsigned g_phs[16 * 32];

// ---------------------------------------------------------------------------
// Helpers
// ---------------------------------------------------------------------------
__device__ __forceinline__ unsigned long long ffma2(
    unsigned long long a, unsigned long long b, unsigned long long c) {
    unsigned long long d;
    asm("fma.rn.f32x2 %0, %1, %2, %3;" : "=l"(d) : "l"(a), "l"(b), "l"(c));
    return d;
}
__device__ __forceinline__ float pair_sum(unsigned long long p) {
    float lo, hi;
    asm("mov.b64 {%0, %1}, %2;" : "=f"(lo), "=f"(hi) : "l"(p));
    return lo + hi;
}
__device__ __forceinline__ float fast_sigmoid(float x) {
    return 1.0f / (1.0f + __expf(-x));
}
__device__ __forceinline__ float fast_tanh(float x) {
    return 2.0f / (1.0f + __expf(-2.0f * x)) - 1.0f;
}
__device__ __forceinline__ uint32_t smem_u32(const void* p) {
    uint32_t a;
    asm("{ .reg .u64 t; cvta.to.shared.u64 t, %1; cvt.u32.u64 %0, t; }"
        : "=r"(a) : "l"(p));
    return a;
}
__device__ __forceinline__ void cp_async16(uint32_t dst, const void* src) {
    asm volatile("cp.async.cg.shared.global [%0], [%1], 16;"
                 :: "r"(dst), "l"(src) : "memory");
}
#define CP_COMMIT() asm volatile("cp.async.commit_group;" ::: "memory")
#define CP_WAIT0()  asm volatile("cp.async.wait_group 0;" ::: "memory")
__device__ __forceinline__ void st_stream(float* p, float v) {
    asm volatile("st.global.cs.f32 [%0], %1;" :: "l"(p), "f"(v) : "memory");
}
__device__ __forceinline__ void half_bar(int half) {
    asm volatile("bar.sync %0, 128;" :: "r"(half + 1) : "memory");
}
// mbarrier ops
__device__ __forceinline__ void mbar_init(uint32_t mbar, unsigned count) {
    asm volatile("mbarrier.init.shared.b64 [%0], %1;"
                 :: "r"(mbar), "r"(count) : "memory");
}
__device__ __forceinline__ void mbar_expect_tx(uint32_t mbar, unsigned bytes) {
    asm volatile("mbarrier.arrive.expect_tx.shared.b64 _, [%0], %1;"
                 :: "r"(mbar), "r"(bytes) : "memory");
}
__device__ __forceinline__ void mbar_wait(uint32_t mbar, unsigned parity) {
    asm volatile(
        "{\n\t.reg .pred P;\n"
        "W_%=:\n\t"
        "mbarrier.try_wait.parity.acquire.cta.shared::cta.b64 P, [%0], %1, 0x989680;\n\t"
        "@P bra D_%=;\n\t"
        "bra W_%=;\n"
        "D_%=:\n\t}"
        :: "r"(mbar), "r"(parity) : "memory");
}
__device__ __forceinline__ void bulk_g2s(uint32_t dst, const void* src,
                                         unsigned bytes, uint32_t mbar) {
    asm volatile(
        "cp.async.bulk.shared::cta.global.mbarrier::complete_tx::bytes "
        "[%0], [%1], %2, [%3];"
        :: "r"(dst), "l"(src), "r"(bytes), "r"(mbar) : "memory");
}

// ---------------------------------------------------------------------------
// Pre-pass: re-layout X into per-(t,grp) contiguous 8KB tiles (natural).
// ---------------------------------------------------------------------------
__global__ void __launch_bounds__(256) xform_x(const float* __restrict__ X) {
    size_t id = (size_t)blockIdx.x * 256 + threadIdx.x;  // one 16B chunk
    int q  = (int)(id & 63);
    int bb = (int)((id >> 6) & 63);
    int t  = (int)(id >> 12);
    float4 v = __ldcg((const float4*)(X + ((size_t)bb * TT + t) * 256 + q * 4));
    *(float4*)(&g_x[t][bb >> 3][bb & 7][0] + q * 4) = v;
}

// ---------------------------------------------------------------------------
// Dual-direction fused LSTM kernel. grid=128, block=256.
// SMEM: [mbar x4][wih d0 48xWPADI][wih d1][hs d0][hs d1][xs d0][xs d1]
// ---------------------------------------------------------------------------
__global__ void __launch_bounds__(256, 1) lstm_fused(
    const float* __restrict__ wih_f, const float* __restrict__ whh_f,
    const float* __restrict__ bih_f, const float* __restrict__ bhh_f,
    const float* __restrict__ wih_b, const float* __restrict__ whh_b,
    const float* __restrict__ bih_b, const float* __restrict__ bhh_b,
    float* __restrict__ out)
{
    extern __shared__ float sm[];
    const int tid  = threadIdx.x;
    const int half = tid >> 7;          // 0 = dir0, 1 = dir1
    const int tidh = tid & 127;
    const int dir  = half;

    // mbarriers: 2 per half (x buf0, x buf1) at the front.
    const uint32_t mb_base = smem_u32(sm) + half * 16;
    const uint32_t mbx0 = mb_base + 0, mbx1 = mb_base + 8;

    float* wih_s = sm + 16 + half * (48 * WPADI);
    float* hs    = sm + 16 + 2 * (48 * WPADI) + half * 4096;
    float* xs    = sm + 16 + 2 * (48 * WPADI) + 2 * 4096 + half * 4096;
    const uint32_t hs_u = smem_u32(hs);
    const uint32_t xs_u = smem_u32(xs);

    const int bx  = blockIdx.x;
    const int grp = bx & 7;
    const int sl  = bx >> 3;            // 0..15
    const int j0  = sl * 16;
    const int gi  = dir * 8 + grp;

    const float* whh = dir ? whh_b : whh_f;
    const float* wih = dir ? wih_b : wih_f;
    const float* bih = dir ? bih_b : bih_f;
    const float* bhh = dir ? bhh_b : bhh_f;

    const int lane  = tid & 31;
    const int warph = tidh >> 5;               // 0..3 within half
    const int jg    = warph * 4 + (lane >> 3); // hidden within slice 0..15
    const int ks    = lane & 7;                // k-slice 0..7 (interleaved)
    const int j     = j0 + jg;
    const int bG    = grp * 8 + ks;
    const int kb    = ks * 4;                  // base column within 32-chunk

    // --- mbarrier init (once, whole CTA). ---
    if (tid == 0) {
        const uint32_t m0 = smem_u32(sm);
#pragma unroll
        for (int i = 0; i < 4; i++) mbar_init(m0 + i * 8, 1u);
    }
    __syncthreads();
    asm volatile("fence.proxy.async.shared::cta;" ::: "memory");

    // --- W_hh slice into REGISTERS: 3 rows, k = c*32 + kb + 0..3 per c. ---
    unsigned long long w0r[16], w1r[16], w2r[16];
#pragma unroll
    for (int g = 0; g < 3; g++) {
        const float* base = whh + (size_t)(g * 256 + j) * 256 + kb;
        unsigned long long* dst = (g == 0) ? w0r : (g == 1) ? w1r : w2r;
#pragma unroll
        for (int c = 0; c < 8; c++) {
            ulonglong2 wv = *(const ulonglong2*)(base + c * 32);
            dst[2 * c]     = wv.x;
            dst[2 * c + 1] = wv.y;
        }
    }

    // --- W_ih slice into SMEM (row-major, padded stride WPADI). ---
    for (int idx = tidh; idx < 48 * 64; idx += 128) {
        int r = idx >> 6, q = idx & 63;
        int grow = (r >> 4) * 256 + j0 + (r & 15);
        float4 v = *(const float4*)(wih + (size_t)grow * 256 + q * 4);
        *(float4*)(wih_s + r * WPADI + q * 4) = v;
    }

    const float bias0 = bih[j]       + bhh[j];
    const float bias1 = bih[256 + j] + bhh[256 + j];
    const float bias2 = bih[512 + j] + bhh[512 + j];

    // Zero h buffer 0; kick bulk copy of x(t0); reset this slice's 4 flags.
    for (int idx = tidh; idx < 2048; idx += 128) hs[idx] = 0.0f;
    if (tidh < 4)
        asm volatile("st.relaxed.gpu.global.u32 [%0], %1;"
                     :: "l"(&g_flag[dir][grp][sl][tidh]), "r"(0u) : "memory");
    if (tidh == 0) {
        const int t0 = dir ? (TT - 1) : 0;
        mbar_expect_tx(mbx0, 8192u);
        bulk_g2s(xs_u, &g_x[t0][grp][0][0], 8192u, mbx0);
    }

    // One-time replay-safe group barrier (16 slices per (dir,grp)).
    half_bar(half);
    if (tidh == 0) {
        unsigned* cnt = &g_cnt[gi * 32];
        unsigned* phs = &g_phs[gi * 32];
        unsigned ph;
        asm volatile("ld.acquire.gpu.global.u32 %0, [%1];"
                     : "=r"(ph) : "l"(phs) : "memory");
        unsigned prev;
        asm volatile("atom.acq_rel.gpu.global.add.u32 %0, [%1], %2;"
                     : "=r"(prev) : "l"(cnt), "r"(1u) : "memory");
        if (prev == 15u) {
            asm volatile("st.relaxed.gpu.global.u32 [%0], %1;"
                         :: "l"(cnt), "r"(0u) : "memory");
            asm volatile("red.release.gpu.global.add.u32 [%0], %1;"
                         :: "l"(phs), "r"(1u) : "memory");
        } else {
            unsigned cur;
            do {
                asm volatile("ld.acquire.gpu.global.u32 %0, [%1];"
                             : "=r"(cur) : "l"(phs) : "memory");
            } while (cur == ph);
        }
    }
    half_bar(half);

    float c_reg = 0.0f;
    // Incremental output pointer (saves per-step IMADs).
    float* outp = out + (size_t)(dir ? (TT - 1) : 0) * (BB * 2 * HH)
                + (size_t)bG * (2 * HH) + dir * HH + j;
    const ptrdiff_t ostep = dir ? -(ptrdiff_t)(BB * 2 * HH)
                                : (ptrdiff_t)(BB * 2 * HH);

    for (int s = 0; s < TT; s++) {
        const int t = dir ? (TT - 1 - s) : s;
        const uint32_t mbx_cur = (s & 1) ? mbx1 : mbx0;

        // --- Elected: issue x(s+1) bulk (async engine; ~0 LSU slots). ---
        if (tidh == 0 && s + 1 < TT) {
            const int tn = dir ? (t - 1) : (t + 1);
            const uint32_t mbx_nxt = ((s + 1) & 1) ? mbx1 : mbx0;
            mbar_expect_tx(mbx_nxt, 8192u);
            bulk_g2s(xs_u + ((s + 1) & 1) * 8192u,
                     &g_x[tn][grp][0][0], 8192u, mbx_nxt);
        }

        // --- Wait x tile (bulk issued during the PREVIOUS step). ---
        mbar_wait(mbx_cur, (unsigned)((s >> 1) & 1));

        // --- gx GEMM first half (c = 0..3). ---
        unsigned long long P0[8], P1[8], P2[8];
#pragma unroll
        for (int b = 0; b < 8; b++) { P0[b] = 0ull; P1[b] = 0ull; P2[b] = 0ull; }

        const float* xb = xs + (s & 1) * 2048;
#pragma unroll
        for (int c = 0; c < 4; c++) {
            const int off = c * 32 + kb;
            ulonglong2 w0 = *(const ulonglong2*)(wih_s + (jg)      * WPADI + off);
            ulonglong2 w1 = *(const ulonglong2*)(wih_s + (16 + jg) * WPADI + off);
            ulonglong2 w2 = *(const ulonglong2*)(wih_s + (32 + jg) * WPADI + off);
#pragma unroll
            for (int b = 0; b < 8; b++) {
                ulonglong2 hv = *(const ulonglong2*)(xb + b * 256 + off);
                P0[b] = ffma2(w0.x, hv.x, P0[b]);
                P1[b] = ffma2(w1.x, hv.x, P1[b]);
                P2[b] = ffma2(w2.x, hv.x, P2[b]);
                P0[b] = ffma2(w0.y, hv.y, P0[b]);
                P1[b] = ffma2(w1.y, hv.y, P1[b]);
                P2[b] = ffma2(w2.y, hv.y, P2[b]);
            }
        }

        // --- Mid-GEMM: PARALLEL poll of 64 per-warp flags, then LDGSTS h. ---
        if (s > 0) {
            if (tidh < 64) {
                const unsigned* f = &g_flag[dir][grp][tidh >> 2][tidh & 3];
                unsigned v;
                do {
                    asm volatile("ld.acquire.gpu.global.u32 %0, [%1];"
                                 : "=r"(v) : "l"(f) : "memory");
                } while (v < (unsigned)s);
            }
            half_bar(half);
            const float* src = &g_h[dir][s & 1][grp][0][0];
            const uint32_t hd = hs_u + ((s & 1) * 2048) * 4;
#pragma unroll
            for (int i = 0; i < 4; i++)
                cp_async16(hd + (tidh + i * 128) * 16, src + (tidh + i * 128) * 4);
            CP_COMMIT();
        }

        // --- gx GEMM second half (c = 4..7). ---
#pragma unroll
        for (int c = 4; c < 8; c++) {
            const int off = c * 32 + kb;
            ulonglong2 w0 = *(const ulonglong2*)(wih_s + (jg)      * WPADI + off);
            ulonglong2 w1 = *(const ulonglong2*)(wih_s + (16 + jg) * WPADI + off);
            ulonglong2 w2 = *(const ulonglong2*)(wih_s + (32 + jg) * WPADI + off);
#pragma unroll
            for (int b = 0; b < 8; b++) {
                ulonglong2 hv = *(const ulonglong2*)(xb + b * 256 + off);
                P0[b] = ffma2(w0.x, hv.x, P0[b]);
                P1[b] = ffma2(w1.x, hv.x, P1[b]);
                P2[b] = ffma2(w2.x, hv.x, P2[b]);
                P0[b] = ffma2(w0.y, hv.y, P0[b]);
                P1[b] = ffma2(w1.y, hv.y, P1[b]);
                P2[b] = ffma2(w2.y, hv.y, P2[b]);
            }
        }

        // --- h tile landed (copied during gx half2). ---
        CP_WAIT0();
        half_bar(half);

        // --- Recurrent GEMM: c-outer / b-inner, W_hh in regs. ---
        const float* hb = hs + (s & 1) * 2048;
#pragma unroll
        for (int c = 0; c < 8; c++) {
            const int off = c * 32 + kb;
#pragma unroll
            for (int b = 0; b < 8; b++) {
                ulonglong2 hv = *(const ulonglong2*)(hb + b * 256 + off);
                P0[b] = ffma2(w0r[2 * c],     hv.x, P0[b]);
                P1[b] = ffma2(w1r[2 * c],     hv.x, P1[b]);
                P2[b] = ffma2(w2r[2 * c],     hv.x, P2[b]);
                P0[b] = ffma2(w0r[2 * c + 1], hv.y, P0[b]);
                P1[b] = ffma2(w1r[2 * c + 1], hv.y, P1[b]);
                P2[b] = ffma2(w2r[2 * c + 1], hv.y, P2[b]);
            }
        }

        float a0[8], a1[8], a2[8];
#pragma unroll
        for (int b = 0; b < 8; b++) {
            a0[b] = pair_sum(P0[b]);
            a1[b] = pair_sum(P1[b]);
            a2[b] = pair_sum(P2[b]);
        }

        // --- Butterfly reduce-scatter over ks: lane ks owns batch b=ks. ---
        const bool hi4 = (ks & 4) != 0;
        float t0a[4], t1a[4], t2a[4];
#pragma unroll
        for (int i = 0; i < 4; i++) {
            float s0 = hi4 ? a0[i] : a0[i + 4];
            float s1 = hi4 ? a1[i] : a1[i + 4];
            float s2 = hi4 ? a2[i] : a2[i + 4];
            t0a[i] = (hi4 ? a0[i + 4] : a0[i]) + __shfl_xor_sync(0xffffffffu, s0, 4);
            t1a[i] = (hi4 ? a1[i + 4] : a1[i]) + __shfl_xor_sync(0xffffffffu, s1, 4);
            t2a[i] = (hi4 ? a2[i + 4] : a2[i]) + __shfl_xor_sync(0xffffffffu, s2, 4);
        }
        const bool hi2 = (ks & 2) != 0;
        float u0[2], u1[2], u2[2];
#pragma unroll
        for (int i = 0; i < 2; i++) {
            float s0 = hi2 ? t0a[i] : t0a[i + 2];
            float s1 = hi2 ? t1a[i] : t1a[i + 2];
            float s2 = hi2 ? t2a[i] : t2a[i + 2];
            u0[i] = (hi2 ? t0a[i + 2] : t0a[i]) + __shfl_xor_sync(0xffffffffu, s0, 2);
            u1[i] = (hi2 ? t1a[i + 2] : t1a[i]) + __shfl_xor_sync(0xffffffffu, s1, 2);
            u2[i] = (hi2 ? t2a[i + 2] : t2a[i]) + __shfl_xor_sync(0xffffffffu, s2, 2);
        }
        const bool hi1 = (ks & 1) != 0;
        float s0 = hi1 ? u0[0] : u0[1];
        float s1 = hi1 ? u1[0] : u1[1];
        float s2 = hi1 ? u2[0] : u2[1];
        float f0 = (hi1 ? u0[1] : u0[0]) + __shfl_xor_sync(0xffffffffu, s0, 1);
        float f1 = (hi1 ? u1[1] : u1[0]) + __shfl_xor_sync(0xffffffffu, s1, 1);
        float f2 = (hi1 ? u2[1] : u2[0]) + __shfl_xor_sync(0xffffffffu, s2, 1);

        f0 += bias0; f1 += bias1; f2 += bias2;

        // --- Coupled-gate pointwise for (hidden j, batch bG). ---
        float ig = fast_sigmoid(f0);
        float cg = fast_tanh(f1);
        float og = fast_sigmoid(f2);
        c_reg = (1.0f - ig) * c_reg + ig * cg;
        float h = og * fast_tanh(c_reg);

        if (s == TT - 1) {
            st_stream(outp, h);
            size_t base = (size_t)TT * BB * 2 * HH;
            st_stream(&out[base + (size_t)bG * (2 * HH) + dir * HH + j], h);
            st_stream(&out[base + (size_t)BB * 2 * HH
                           + (size_t)bG * (2 * HH) + dir * HH + j], c_reg);
        } else {
            // PER-WARP publish + release: no producer half_bar.
            g_h[dir][(s + 1) & 1][grp][ks][j] = h;
            asm volatile("bar.warp.sync 0xffffffff;" ::: "memory");
            if (lane == 0)
                asm volatile("st.release.gpu.global.u32 [%0], %1;"
                             :: "l"(&g_flag[dir][grp][sl][warph]),
                                "r"((unsigned)(s + 1)) : "memory");
            st_stream(outp, h);
        }
        outp += ostep;
    }
}

// ---------------------------------------------------------------------------
// Launch. Inputs: X, wih_f, whh_f, bih_f, bhh_f, wih_b, whh_b, bih_b, bhh_b.
// Output fp32: out[T,B,2H] ++ hn[1,B,2H] ++ cn[1,B,2H].
// ---------------------------------------------------------------------------
extern "C" void kernel_launch(void* const* d_in, const int* in_sizes, int n_in,
                              void* d_out, int out_size) {
    const float* X     = (const float*)d_in[0];
    const float* wih_f = (const float*)d_in[1];
    const float* whh_f = (const float*)d_in[2];
    const float* bih_f = (const float*)d_in[3];
    const float* bhh_f = (const float*)d_in[4];
    const float* wih_b = (const float*)d_in[5];
    const float* whh_b = (const float*)d_in[6];
    const float* bih_b = (const float*)d_in[7];
    const float* bhh_b = (const float*)d_in[8];
    float* out = (float*)d_out;

    // Pre-pass: 1024*64*64 16B chunks -> 16384 blocks x 256 threads.
    xform_x<<<16384, 256>>>(X);

    const int smem = (16 + 2 * 48 * WPADI + 4 * 4096) * (int)sizeof(float);
    cudaFuncSetAttribute(lstm_fused, cudaFuncAttributeMaxDynamicSharedMemorySize,
                         smem);
    lstm_fused<<<128, 256, smem>>>(wih_f, whh_f, bih_f, bhh_f,
                                   wih_b, whh_b, bih_b, bhh_b, out);
}

// round 15
// speedup vs baseline: 1.1405x; 1.1405x over previous
#include <cuda_runtime.h>
#include <cstdint>
#include <cstddef>

// Problem dims
#define TT 1024
#define BB 64
#define HH 256
#define WPADI 260   // wih SMEM row stride (floats): 4-bank shift per row

// Dual-direction fused persistent kernel (R13 base + padded W_ih rows).
// 128 CTAs x 256 threads. Warps 0-3 = dir0 half, warps 4-7 = dir1 half.
// Each half: 16 hidden (48 gate rows) x 8 batches, K=256 both GEMMs.
// Thread (jg 0..15, ks 0..7) owns k-indices {c*32 + ks*4 + 0..3}: warp h/x
// loads are 1 wavefront (contiguous 128B line); padded wih rows make the
// w loads 1 wavefront too (R13 had 4-way bank conflicts there).
//   x tiles: cp.async.bulk from g_x pre-pass, mbarrier, 1 step ahead.
//   h tiles: LDGSTS mid-GEMM after PARALLEL 16-flag poll (R13-proven).

__device__ float    g_x[TT][8][8][256];     // [t][grp][b][k] natural (64 MB)
__device__ float    g_h[2][2][8][8][256];   // [dir][buf][grp][b][k]
__device__ unsigned g_flag[2][8][16];       // per (dir,grp,slice) step flag
__device__ unsigned g_cnt[16 * 32];         // init barrier (128B-strided)
__device__ unsigned g_phs[16 * 32];

// ---------------------------------------------------------------------------
// Helpers
// ---------------------------------------------------------------------------
__device__ __forceinline__ unsigned long long ffma2(
    unsigned long long a, unsigned long long b, unsigned long long c) {
    unsigned long long d;
    asm("fma.rn.f32x2 %0, %1, %2, %3;" : "=l"(d) : "l"(a), "l"(b), "l"(c));
    return d;
}
__device__ __forceinline__ float pair_sum(unsigned long long p) {
    float lo, hi;
    asm("mov.b64 {%0, %1}, %2;" : "=f"(lo), "=f"(hi) : "l"(p));
    return lo + hi;
}
__device__ __forceinline__ float fast_sigmoid(float x) {
    return 1.0f / (1.0f + __expf(-x));
}
__device__ __forceinline__ float fast_tanh(float x) {
    return 2.0f / (1.0f + __expf(-2.0f * x)) - 1.0f;
}
__device__ __forceinline__ uint32_t smem_u32(const void* p) {
    uint32_t a;
    asm("{ .reg .u64 t; cvta.to.shared.u64 t, %1; cvt.u32.u64 %0, t; }"
        : "=r"(a) : "l"(p));
    return a;
}
__device__ __forceinline__ void cp_async16(uint32_t dst, const void* src) {
    asm volatile("cp.async.cg.shared.global [%0], [%1], 16;"
                 :: "r"(dst), "l"(src) : "memory");
}
#define CP_COMMIT() asm volatile("cp.async.commit_group;" ::: "memory")
#define CP_WAIT0()  asm volatile("cp.async.wait_group 0;" ::: "memory")
__device__ __forceinline__ void st_stream(float* p, float v) {
    asm volatile("st.global.cs.f32 [%0], %1;" :: "l"(p), "f"(v) : "memory");
}
__device__ __forceinline__ void half_bar(int half) {
    asm volatile("bar.sync %0, 128;" :: "r"(half + 1) : "memory");
}
// mbarrier ops
__device__ __forceinline__ void mbar_init(uint32_t mbar, unsigned count) {
    asm volatile("mbarrier.init.shared.b64 [%0], %1;"
                 :: "r"(mbar), "r"(count) : "memory");
}
__device__ __forceinline__ void mbar_expect_tx(uint32_t mbar, unsigned bytes) {
    asm volatile("mbarrier.arrive.expect_tx.shared.b64 _, [%0], %1;"
                 :: "r"(mbar), "r"(bytes) : "memory");
}
__device__ __forceinline__ void mbar_wait(uint32_t mbar, unsigned parity) {
    asm volatile(
        "{\n\t.reg .pred P;\n"
        "W_%=:\n\t"
        "mbarrier.try_wait.parity.acquire.cta.shared::cta.b64 P, [%0], %1, 0x989680;\n\t"
        "@P bra D_%=;\n\t"
        "bra W_%=;\n"
        "D_%=:\n\t}"
        :: "r"(mbar), "r"(parity) : "memory");
}
__device__ __forceinline__ void bulk_g2s(uint32_t dst, const void* src,
                                         unsigned bytes, uint32_t mbar) {
    asm volatile(
        "cp.async.bulk.shared::cta.global.mbarrier::complete_tx::bytes "
        "[%0], [%1], %2, [%3];"
        :: "r"(dst), "l"(src), "r"(bytes), "r"(mbar) : "memory");
}

// ---------------------------------------------------------------------------
// Pre-pass: re-layout X into per-(t,grp) contiguous 8KB tiles (natural).
// ---------------------------------------------------------------------------
__global__ void __launch_bounds__(256) xform_x(const float* __restrict__ X) {
    size_t id = (size_t)blockIdx.x * 256 + threadIdx.x;  // one 16B chunk
    int q  = (int)(id & 63);
    int bb = (int)((id >> 6) & 63);
    int t  = (int)(id >> 12);
    float4 v = __ldcg((const float4*)(X + ((size_t)bb * TT + t) * 256 + q * 4));
    *(float4*)(&g_x[t][bb >> 3][bb & 7][0] + q * 4) = v;
}

// ---------------------------------------------------------------------------
// Dual-direction fused LSTM kernel. grid=128, block=256.
// SMEM: [mbar x4][wih d0 48xWPADI][wih d1][hs d0][hs d1][xs d0][xs d1]
// ---------------------------------------------------------------------------
__global__ void __launch_bounds__(256, 1) lstm_fused(
    const float* __restrict__ wih_f, const float* __restrict__ whh_f,
    const float* __restrict__ bih_f, const float* __restrict__ bhh_f,
    const float* __restrict__ wih_b, const float* __restrict__ whh_b,
    const float* __restrict__ bih_b, const float* __restrict__ bhh_b,
    float* __restrict__ out)
{
    extern __shared__ float sm[];
    const int tid  = threadIdx.x;
    const int half = tid >> 7;          // 0 = dir0, 1 = dir1
    const int tidh = tid & 127;
    const int dir  = half;

    // mbarriers: 2 per half (x buf0, x buf1) at the front.
    const uint32_t mb_base = smem_u32(sm) + half * 16;
    const uint32_t mbx0 = mb_base + 0, mbx1 = mb_base + 8;

    float* wih_s = sm + 16 + half * (48 * WPADI);
    float* hs    = sm + 16 + 2 * (48 * WPADI) + half * 4096;
    float* xs    = sm + 16 + 2 * (48 * WPADI) + 2 * 4096 + half * 4096;
    const uint32_t hs_u = smem_u32(hs);
    const uint32_t xs_u = smem_u32(xs);

    const int bx  = blockIdx.x;
    const int grp = bx & 7;
    const int sl  = bx >> 3;            // 0..15
    const int j0  = sl * 16;
    const int gi  = dir * 8 + grp;

    const float* whh = dir ? whh_b : whh_f;
    const float* wih = dir ? wih_b : wih_f;
    const float* bih = dir ? bih_b : bih_f;
    const float* bhh = dir ? bhh_b : bhh_f;

    const int lane  = tid & 31;
    const int warph = tidh >> 5;               // 0..3 within half
    const int jg    = warph * 4 + (lane >> 3); // hidden within slice 0..15
    const int ks    = lane & 7;                // k-slice 0..7 (interleaved)
    const int j     = j0 + jg;
    const int bG    = grp * 8 + ks;
    const int kb    = ks * 4;                  // base column within 32-chunk

    // --- mbarrier init (once, whole CTA). ---
    if (tid == 0) {
        const uint32_t m0 = smem_u32(sm);
#pragma unroll
        for (int i = 0; i < 4; i++) mbar_init(m0 + i * 8, 1u);
    }
    __syncthreads();
    asm volatile("fence.proxy.async.shared::cta;" ::: "memory");

    // --- W_hh slice into REGISTERS: 3 rows, k = c*32 + kb + 0..3 per c. ---
    unsigned long long w0r[16], w1r[16], w2r[16];
#pragma unroll
    for (int g = 0; g < 3; g++) {
        const float* base = whh + (size_t)(g * 256 + j) * 256 + kb;
        unsigned long long* dst = (g == 0) ? w0r : (g == 1) ? w1r : w2r;
#pragma unroll
        for (int c = 0; c < 8; c++) {
            ulonglong2 wv = *(const ulonglong2*)(base + c * 32);
            dst[2 * c]     = wv.x;
            dst[2 * c + 1] = wv.y;
        }
    }

    // --- W_ih slice into SMEM (row-major, padded stride WPADI). ---
    for (int idx = tidh; idx < 48 * 64; idx += 128) {
        int r = idx >> 6, q = idx & 63;
        int grow = (r >> 4) * 256 + j0 + (r & 15);
        float4 v = *(const float4*)(wih + (size_t)grow * 256 + q * 4);
        *(float4*)(wih_s + r * WPADI + q * 4) = v;
    }

    const float bias0 = bih[j]       + bhh[j];
    const float bias1 = bih[256 + j] + bhh[256 + j];
    const float bias2 = bih[512 + j] + bhh[512 + j];

    // Zero h buffer 0; kick bulk copy of x(t0) into xs buffer 0; reset flag.
    for (int idx = tidh; idx < 2048; idx += 128) hs[idx] = 0.0f;
    if (tidh == 0) {
        const int t0 = dir ? (TT - 1) : 0;
        mbar_expect_tx(mbx0, 8192u);
        bulk_g2s(xs_u, &g_x[t0][grp][0][0], 8192u, mbx0);
        asm volatile("st.relaxed.gpu.global.u32 [%0], %1;"
                     :: "l"(&g_flag[dir][grp][sl]), "r"(0u) : "memory");
    }

    // One-time replay-safe group barrier (16 slices per (dir,grp)).
    half_bar(half);
    if (tidh == 0) {
        unsigned* cnt = &g_cnt[gi * 32];
        unsigned* phs = &g_phs[gi * 32];
        unsigned ph;
        asm volatile("ld.acquire.gpu.global.u32 %0, [%1];"
                     : "=r"(ph) : "l"(phs) : "memory");
        unsigned prev;
        asm volatile("atom.acq_rel.gpu.global.add.u32 %0, [%1], %2;"
                     : "=r"(prev) : "l"(cnt), "r"(1u) : "memory");
        if (prev == 15u) {
            asm volatile("st.relaxed.gpu.global.u32 [%0], %1;"
                         :: "l"(cnt), "r"(0u) : "memory");
            asm volatile("red.release.gpu.global.add.u32 [%0], %1;"
                         :: "l"(phs), "r"(1u) : "memory");
        } else {
            unsigned cur;
            do {
                asm volatile("ld.acquire.gpu.global.u32 %0, [%1];"
                             : "=r"(cur) : "l"(phs) : "memory");
            } while (cur == ph);
        }
    }
    half_bar(half);

    float c_reg = 0.0f;
    // Incremental output pointer (saves per-step IMADs).
    float* outp = out + (size_t)(dir ? (TT - 1) : 0) * (BB * 2 * HH)
                + (size_t)bG * (2 * HH) + dir * HH + j;
    const ptrdiff_t ostep = dir ? -(ptrdiff_t)(BB * 2 * HH)
                                : (ptrdiff_t)(BB * 2 * HH);

    for (int s = 0; s < TT; s++) {
        const int t = dir ? (TT - 1 - s) : s;
        const uint32_t mbx_cur = (s & 1) ? mbx1 : mbx0;

        // --- Elected: issue x(s+1) bulk (async engine; ~0 LSU slots). ---
        if (tidh == 0 && s + 1 < TT) {
            const int tn = dir ? (t - 1) : (t + 1);
            const uint32_t mbx_nxt = ((s + 1) & 1) ? mbx1 : mbx0;
            mbar_expect_tx(mbx_nxt, 8192u);
            bulk_g2s(xs_u + ((s + 1) & 1) * 8192u,
                     &g_x[tn][grp][0][0], 8192u, mbx_nxt);
        }

        // --- Wait x tile (bulk issued during the PREVIOUS step). ---
        mbar_wait(mbx_cur, (unsigned)((s >> 1) & 1));

        // --- gx GEMM first half (c = 0..3). ---
        unsigned long long P0[8], P1[8], P2[8];
#pragma unroll
        for (int b = 0; b < 8; b++) { P0[b] = 0ull; P1[b] = 0ull; P2[b] = 0ull; }

        const float* xb = xs + (s & 1) * 2048;
#pragma unroll
        for (int c = 0; c < 4; c++) {
            const int off = c * 32 + kb;
            ulonglong2 w0 = *(const ulonglong2*)(wih_s + (jg)      * WPADI + off);
            ulonglong2 w1 = *(const ulonglong2*)(wih_s + (16 + jg) * WPADI + off);
            ulonglong2 w2 = *(const ulonglong2*)(wih_s + (32 + jg) * WPADI + off);
#pragma unroll
            for (int b = 0; b < 8; b++) {
                ulonglong2 hv = *(const ulonglong2*)(xb + b * 256 + off);
                P0[b] = ffma2(w0.x, hv.x, P0[b]);
                P1[b] = ffma2(w1.x, hv.x, P1[b]);
                P2[b] = ffma2(w2.x, hv.x, P2[b]);
                P0[b] = ffma2(w0.y, hv.y, P0[b]);
                P1[b] = ffma2(w1.y, hv.y, P1[b]);
                P2[b] = ffma2(w2.y, hv.y, P2[b]);
            }
        }

        // --- Mid-GEMM: PARALLEL poll of 16 peer flags, then LDGSTS h tile. ---
        if (s > 0) {
            if (tidh < 16) {
                const unsigned* f = &g_flag[dir][grp][tidh];
                unsigned v;
                do {
                    asm volatile("ld.acquire.gpu.global.u32 %0, [%1];"
                                 : "=r"(v) : "l"(f) : "memory");
                } while (v < (unsigned)s);
            }
            half_bar(half);
            const float* src = &g_h[dir][s & 1][grp][0][0];
            const uint32_t hd = hs_u + ((s & 1) * 2048) * 4;
#pragma unroll
            for (int i = 0; i < 4; i++)
                cp_async16(hd + (tidh + i * 128) * 16, src + (tidh + i * 128) * 4);
            CP_COMMIT();
        }

        // --- gx GEMM second half (c = 4..7). ---
#pragma unroll
        for (int c = 4; c < 8; c++) {
            const int off = c * 32 + kb;
            ulonglong2 w0 = *(const ulonglong2*)(wih_s + (jg)      * WPADI + off);
            ulonglong2 w1 = *(const ulonglong2*)(wih_s + (16 + jg) * WPADI + off);
            ulonglong2 w2 = *(const ulonglong2*)(wih_s + (32 + jg) * WPADI + off);
#pragma unroll
            for (int b = 0; b < 8; b++) {
                ulonglong2 hv = *(const ulonglong2*)(xb + b * 256 + off);
                P0[b] = ffma2(w0.x, hv.x, P0[b]);
                P1[b] = ffma2(w1.x, hv.x, P1[b]);
                P2[b] = ffma2(w2.x, hv.x, P2[b]);
                P0[b] = ffma2(w0.y, hv.y, P0[b]);
                P1[b] = ffma2(w1.y, hv.y, P1[b]);
                P2[b] = ffma2(w2.y, hv.y, P2[b]);
            }
        }

        // --- h tile landed (copied during gx half2). ---
        CP_WAIT0();
        half_bar(half);

        // --- Recurrent GEMM: c-outer / b-inner, W_hh in regs. ---
        const float* hb = hs + (s & 1) * 2048;
#pragma unroll
        for (int c = 0; c < 8; c++) {
            const int off = c * 32 + kb;
#pragma unroll
            for (int b = 0; b < 8; b++) {
                ulonglong2 hv = *(const ulonglong2*)(hb + b * 256 + off);
                P0[b] = ffma2(w0r[2 * c],     hv.x, P0[b]);
                P1[b] = ffma2(w1r[2 * c],     hv.x, P1[b]);
                P2[b] = ffma2(w2r[2 * c],     hv.x, P2[b]);
                P0[b] = ffma2(w0r[2 * c + 1], hv.y, P0[b]);
                P1[b] = ffma2(w1r[2 * c + 1], hv.y, P1[b]);
                P2[b] = ffma2(w2r[2 * c + 1], hv.y, P2[b]);
            }
        }

        float a0[8], a1[8], a2[8];
#pragma unroll
        for (int b = 0; b < 8; b++) {
            a0[b] = pair_sum(P0[b]);
            a1[b] = pair_sum(P1[b]);
            a2[b] = pair_sum(P2[b]);
        }

        // --- Butterfly reduce-scatter over ks: lane ks owns batch b=ks. ---
        const bool hi4 = (ks & 4) != 0;
        float t0a[4], t1a[4], t2a[4];
#pragma unroll
        for (int i = 0; i < 4; i++) {
            float s0 = hi4 ? a0[i] : a0[i + 4];
            float s1 = hi4 ? a1[i] : a1[i + 4];
            float s2 = hi4 ? a2[i] : a2[i + 4];
            t0a[i] = (hi4 ? a0[i + 4] : a0[i]) + __shfl_xor_sync(0xffffffffu, s0, 4);
            t1a[i] = (hi4 ? a1[i + 4] : a1[i]) + __shfl_xor_sync(0xffffffffu, s1, 4);
            t2a[i] = (hi4 ? a2[i + 4] : a2[i]) + __shfl_xor_sync(0xffffffffu, s2, 4);
        }
        const bool hi2 = (ks & 2) != 0;
        float u0[2], u1[2], u2[2];
#pragma unroll
        for (int i = 0; i < 2; i++) {
            float s0 = hi2 ? t0a[i] : t0a[i + 2];
            float s1 = hi2 ? t1a[i] : t1a[i + 2];
            float s2 = hi2 ? t2a[i] : t2a[i + 2];
            u0[i] = (hi2 ? t0a[i + 2] : t0a[i]) + __shfl_xor_sync(0xffffffffu, s0, 2);
            u1[i] = (hi2 ? t1a[i + 2] : t1a[i]) + __shfl_xor_sync(0xffffffffu, s1, 2);
            u2[i] = (hi2 ? t2a[i + 2] : t2a[i]) + __shfl_xor_sync(0xffffffffu, s2, 2);
        }
        const bool hi1 = (ks & 1) != 0;
        float s0 = hi1 ? u0[0] : u0[1];
        float s1 = hi1 ? u1[0] : u1[1];
        float s2 = hi1 ? u2[0] : u2[1];
        float f0 = (hi1 ? u0[1] : u0[0]) + __shfl_xor_sync(0xffffffffu, s0, 1);
        float f1 = (hi1 ? u1[1] : u1[0]) + __shfl_xor_sync(0xffffffffu, s1, 1);
        float f2 = (hi1 ? u2[1] : u2[0]) + __shfl_xor_sync(0xffffffffu, s2, 1);

        f0 += bias0; f1 += bias1; f2 += bias2;

        // --- Coupled-gate pointwise for (hidden j, batch bG). ---
        float ig = fast_sigmoid(f0);
        float cg = fast_tanh(f1);
        float og = fast_sigmoid(f2);
        c_reg = (1.0f - ig) * c_reg + ig * cg;
        float h = og * fast_tanh(c_reg);

        if (s == TT - 1) {
            st_stream(outp, h);
            size_t base = (size_t)TT * BB * 2 * HH;
            st_stream(&out[base + (size_t)bG * (2 * HH) + dir * HH + j], h);
            st_stream(&out[base + (size_t)BB * 2 * HH
                           + (size_t)bG * (2 * HH) + dir * HH + j], c_reg);
        } else {
            // Publish h slice; half barrier; release flag; stream output.
            g_h[dir][(s + 1) & 1][grp][ks][j] = h;
            half_bar(half);
            if (tidh == 0)
                asm volatile("st.release.gpu.global.u32 [%0], %1;"
                             :: "l"(&g_flag[dir][grp][sl]),
                                "r"((unsigned)(s + 1)) : "memory");
            st_stream(outp, h);
        }
        outp += ostep;
    }
}

// ---------------------------------------------------------------------------
// Launch. Inputs: X, wih_f, whh_f, bih_f, bhh_f, wih_b, whh_b, bih_b, bhh_b.
// Output fp32: out[T,B,2H] ++ hn[1,B,2H] ++ cn[1,B,2H].
// ---------------------------------------------------------------------------
extern "C" void kernel_launch(void* const* d_in, const int* in_sizes, int n_in,
                              void* d_out, int out_size) {
    const float* X     = (const float*)d_in[0];
    const float* wih_f = (const float*)d_in[1];
    const float* whh_f = (const float*)d_in[2];
    const float* bih_f = (const float*)d_in[3];
    const float* bhh_f = (const float*)d_in[4];
    const float* wih_b = (const float*)d_in[5];
    const float* whh_b = (const float*)d_in[6];
    const float* bih_b = (const float*)d_in[7];
    const float* bhh_b = (const float*)d_in[8];
    float* out = (float*)d_out;

    // Pre-pass: 1024*64*64 16B chunks -> 16384 blocks x 256 threads.
    xform_x<<<16384, 256>>>(X);

    const int smem = (16 + 2 * 48 * WPADI + 4 * 4096) * (int)sizeof(float);
    cudaFuncSetAttribute(lstm_fused, cudaFuncAttributeMaxDynamicSharedMemorySize,
                         smem);
    lstm_fused<<<128, 256, smem>>>(wih_f, whh_f, bih_f, bhh_f,
                                   wih_b, whh_b, bih_b, bhh_b, out);
}